// round 4
// baseline (speedup 1.0000x reference)
#include <cuda_runtime.h>
#include <math.h>

#define IMG    224
#define PSIDE  112
#define P      12544
#define BATCH  32
#define NC     10
#define TPB    256
#define BLKX   49               // 12544 / 256
#define NBLOCKS (BLKX * BATCH)  // 1568
#define NWARP  8

__device__ float    g_part[BATCH * BLKX * NC];
__device__ unsigned g_ctr = 0;

__device__ __forceinline__ float ldcg(const float* p) {
    float v; asm volatile("ld.global.cg.f32 %0, [%1];" : "=f"(v) : "l"(p)); return v;
}

// Closed-form 4-qubit block (circuit factorizes into pairs {0,1},{2,3};
// final RZ is a pure phase):
//   Z0 = cos(d0+p0)
//   Z1 = cos(d0+p0) * cos(p1) * cos(d1)
//   Z2 = cos(p4)cos(d2) + sin(p2)sin(p4) * sin(d2) * sin(d3+p3)
//   Z3 = cos(d2) * cos(d3+p3)
// consts c[7] = {cos p0, sin p0, cos p1, cos p3, sin p3, cos p4, sin p2*sin p4}
__device__ __forceinline__ void qblock(const float* __restrict__ c,
                                       float d0, float d1, float d2, float d3,
                                       float& z0, float& z1, float& z2, float& z3) {
    float s0, c0; __sincosf(d0, &s0, &c0);
    float cA = c0 * c[0] - s0 * c[1];
    z0 = cA;
    z1 = cA * c[2] * __cosf(d1);
    float s2, c2; __sincosf(d2, &s2, &c2);
    float s3, c3; __sincosf(d3, &s3, &c3);
    float cB = c3 * c[3] - s3 * c[4];
    float sB = s3 * c[3] + c3 * c[4];
    z2 = c[5] * c2 + c[6] * s2 * sB;
    z3 = c2 * cB;
}

__global__ void __launch_bounds__(TPB)
k_fused(const float* __restrict__ x,
        const float* __restrict__ rl1, const float* __restrict__ rl2,
        const float* __restrict__ W,   const float* __restrict__ bias,
        float* __restrict__ out) {
    const int tid = threadIdx.x;
    const int blk = blockIdx.x;                 // patch tile [0,49)
    const int b   = blockIdx.y;                 // batch
    const int p   = blk * TPB + tid;            // patch [0, 12544)
    const int r   = p / PSIDE;
    const int pc  = p - r * PSIDE;
    const bool edge = (pc == PSIDE - 1);

    __shared__ float  s_c[14];
    __shared__ float4 s_f[TPB];                 // staged features

    if (tid < 2) {
        const float* prm = (tid == 0) ? rl1 : rl2;
        float* c = s_c + tid * 7;
        float s, co;
        __sincosf(__ldg(prm + 0), &s, &co); c[0] = co; c[1] = s;
        c[2] = __cosf(__ldg(prm + 1));
        __sincosf(__ldg(prm + 3), &s, &co); c[3] = co; c[4] = s;
        float s4, c4; __sincosf(__ldg(prm + 4), &s4, &c4);
        c[5] = c4;
        c[6] = __sinf(__ldg(prm + 2)) * s4;
    }

    // ---- compute phase: 3 loads per thread ----
    const float* row0 = x + (size_t)b * (IMG * IMG) + (2 * r) * IMG + 2 * pc;
    const float2 A = *(const float2*)row0;          // x[2r][2pc], x[2r][2pc+1]
    const float2 B = *(const float2*)(row0 + IMG);  // x[2r+1][2pc], x[2r+1][2pc+1]
    const float  e = __ldg(row0 + 2);               // x[2r][2pc+2] (in bounds always)

    const float f0 = A.x;
    const float f1 = A.y;
    const float f2 = edge ? B.x : e;
    const float f3 = edge ? B.y : B.x;

    __syncthreads();            // s_c ready

    float m0, m1, m2, m3, n0, n1, n2, n3;
    qblock(s_c,     f0, f1, f2, f3, m0, m1, m2, m3);
    qblock(s_c + 7, m0, m1, m2, m3, n0, n1, n2, n3);
    s_f[tid] = make_float4(m0 + n0, m1 + n1, m2 + n2, m3 + n3);

    __syncthreads();            // features staged

    // ---- GEMV phase: warp-per-class over this block's 256 patches ----
    const int warp = tid >> 5, lane = tid & 31;
    const float4* __restrict__ W4 = (const float4*)W;
    const int pbase = blk * TPB;

    #pragma unroll
    for (int c = warp; c < NC; c += NWARP) {
        float acc = 0.f;
        #pragma unroll
        for (int k = 0; k < TPB / 32; k++) {
            const int j = k * 32 + lane;
            float4 w = __ldg(W4 + (size_t)c * P + pbase + j);
            float4 f = s_f[j];
            acc = fmaf(f.x, w.x, fmaf(f.y, w.y, fmaf(f.z, w.z, fmaf(f.w, w.w, acc))));
        }
        #pragma unroll
        for (int off = 16; off > 0; off >>= 1)
            acc += __shfl_down_sync(0xffffffffu, acc, off);
        if (lane == 0)
            g_part[(b * BLKX + blk) * NC + c] = acc;
    }

    // ---- grid-wide finalize by last block ----
    __shared__ int lastFlag;
    __threadfence();
    __syncthreads();
    if (tid == 0) lastFlag = (atomicAdd(&g_ctr, 1u) == NBLOCKS - 1);
    __syncthreads();
    if (!lastFlag) return;

    __threadfence();
    if (tid < BATCH) {
        float lg[NC];
        #pragma unroll
        for (int c = 0; c < NC; c++) {
            float s = __ldg(bias + c);
            const float* pp = g_part + (tid * BLKX) * NC + c;
            #pragma unroll 7
            for (int t = 0; t < BLKX; t++) s += ldcg(pp + t * NC);
            lg[c] = s;
        }
        float mx = lg[0];
        #pragma unroll
        for (int c = 1; c < NC; c++) mx = fmaxf(mx, lg[c]);
        float se = 0.f;
        #pragma unroll
        for (int c = 0; c < NC; c++) se += expf(lg[c] - mx);
        const float lse = logf(se);
        #pragma unroll
        for (int c = 0; c < NC; c++) out[tid * NC + c] = lg[c] - mx - lse;
    }
    if (tid == 0) g_ctr = 0;    // reset for next graph replay
}

extern "C" void kernel_launch(void* const* d_in, const int* in_sizes, int n_in,
                              void* d_out, int out_size) {
    const float* x    = (const float*)d_in[0];
    const float* rl1  = (const float*)d_in[1];
    const float* rl2  = (const float*)d_in[2];
    const float* W    = (const float*)d_in[3];
    const float* bias = (const float*)d_in[4];
    float* out        = (float*)d_out;

    k_fused<<<dim3(BLKX, BATCH), TPB>>>(x, rl1, rl2, W, bias, out);
}

// round 5
// speedup vs baseline: 2.4647x; 2.4647x over previous
#include <cuda_runtime.h>
#include <math.h>

#define IMG    224
#define PSIDE  112
#define P      12544
#define BATCH  32
#define NC     10
#define KP     4                  // patches per thread (row-consecutive)
#define GB     4                  // batches per thread
#define ROWG   (PSIDE / KP)       // 28 patch-groups per row
#define PG     (P / KP)           // 3136 patch-groups
#define TPB    64
#define BLKX   (PG / TPB)         // 49
#define NBG    (BATCH / GB)       // 8
#define NBLOCKS (BLKX * NBG)      // 392
#define BLKS   52                 // padded stride (multiple of 4) for g_part

typedef unsigned long long u64;

__device__ float    g_part[NC * BATCH * BLKS];
__device__ unsigned g_ctr = 0;

#define PK(d, lo, hi)  asm("mov.b64 %0, {%1, %2};" : "=l"(d) : "f"(lo), "f"(hi))
#define FMA2(d, a, b, c) asm("fma.rn.f32x2 %0, %1, %2, %3;" : "=l"(d) : "l"(a), "l"(b), "l"(c))
#define ADD2(d, a, b)  asm("add.rn.f32x2 %0, %1, %2;" : "=l"(d) : "l"(a), "l"(b))

__device__ __forceinline__ float ldcg(const float* p) {
    float v; asm volatile("ld.global.cg.f32 %0, [%1];" : "=f"(v) : "l"(p)); return v;
}
__device__ __forceinline__ float4 ldcg4(const float* p) {
    float4 v;
    asm volatile("ld.global.cg.v4.f32 {%0,%1,%2,%3}, [%4];"
                 : "=f"(v.x), "=f"(v.y), "=f"(v.z), "=f"(v.w) : "l"(p));
    return v;
}

// Closed-form 4-qubit block (circuit factorizes into pairs {0,1},{2,3};
// final RZ is a pure phase):
//   Z0 = cos(d0+p0);  Z1 = Z0 * cos(p1) * cos(d1)
//   Z2 = cos(p4)cos(d2) + sin(p2)sin(p4) * sin(d2) * sin(d3+p3)
//   Z3 = cos(d2) * cos(d3+p3)
// consts c[7] = {cos p0, sin p0, cos p1, cos p3, sin p3, cos p4, sin p2*sin p4}
__device__ __forceinline__ void qblock(const float c[7],
                                       float d0, float d1, float d2, float d3,
                                       float& z0, float& z1, float& z2, float& z3) {
    float s0, c0; __sincosf(d0, &s0, &c0);
    float cA = c0 * c[0] - s0 * c[1];
    z0 = cA;
    z1 = cA * c[2] * __cosf(d1);
    float s2, c2; __sincosf(d2, &s2, &c2);
    float s3, c3; __sincosf(d3, &s3, &c3);
    float cB = c3 * c[3] - s3 * c[4];
    float sB = s3 * c[3] + c3 * c[4];
    z2 = c[5] * c2 + c[6] * s2 * sB;
    z3 = c2 * cB;
}

__device__ __forceinline__ void make_consts(const float* __restrict__ prm, float c[7]) {
    float s, co;
    __sincosf(__ldg(prm + 0), &s, &co); c[0] = co; c[1] = s;
    c[2] = __cosf(__ldg(prm + 1));
    __sincosf(__ldg(prm + 3), &s, &co); c[3] = co; c[4] = s;
    float s4, c4; __sincosf(__ldg(prm + 4), &s4, &c4);
    c[5] = c4;
    c[6] = __sinf(__ldg(prm + 2)) * s4;
}

__global__ void __launch_bounds__(TPB)
k_fused(const float* __restrict__ x,
        const float* __restrict__ rl1, const float* __restrict__ rl2,
        const float* __restrict__ W,   const float* __restrict__ bias,
        float* __restrict__ out) {
    const int tid  = threadIdx.x;
    const int blk  = blockIdx.x;
    const int pg   = blk * TPB + tid;              // patch-group [0, 3136)
    const int b0   = blockIdx.y * GB;              // first batch
    const int r    = pg / ROWG;                    // patch row [0, 112)
    const int g    = pg - r * ROWG;                // group in row [0, 28)
    const bool edge = (g == ROWG - 1);

    float c1[7], c2[7];
    make_consts(rl1, c1);
    make_consts(rl2, c2);

    // x loads: row0[0..7] (+row0[8] non-edge), row1[0..7] per batch.
    const float* Xb = x + (size_t)b0 * (IMG * IMG) + (2 * r) * IMG + g * (2 * KP);
    float4 r0a[GB], r0b[GB], r1a[GB], r1b[GB]; float f8[GB];
    #pragma unroll
    for (int q = 0; q < GB; q++) {
        const float* p0 = Xb + q * (IMG * IMG);
        const float* p1 = p0 + IMG;
        r0a[q] = *(const float4*)p0;
        r0b[q] = *(const float4*)(p0 + 4);
        r1a[q] = *(const float4*)p1;
        r1b[q] = *(const float4*)(p1 + 4);
        f8[q]  = edge ? 0.f : __ldg(p0 + 8);
    }

    // Packed accumulators: acc2[q][cp] holds (class 2cp, class 2cp+1).
    u64 acc2[GB][NC / 2];
    #pragma unroll
    for (int q = 0; q < GB; q++)
        #pragma unroll
        for (int cp = 0; cp < NC / 2; cp++) acc2[q][cp] = 0ull;

    const float4* __restrict__ W4 = (const float4*)W;
    const int pbase = r * PSIDE + g * KP;

    #pragma unroll
    for (int i = 0; i < KP; i++) {
        // features for 4 batches of this patch
        u64 zr[4][GB];                      // replicated packs (feat, q)
        #pragma unroll
        for (int q = 0; q < GB; q++) {
            float f0, f1, f2, f3;
            if      (i == 0) { f0 = r0a[q].x; f1 = r0a[q].y; f2 = r0a[q].z; f3 = r1a[q].x; }
            else if (i == 1) { f0 = r0a[q].z; f1 = r0a[q].w; f2 = r0b[q].x; f3 = r1a[q].z; }
            else if (i == 2) { f0 = r0b[q].x; f1 = r0b[q].y; f2 = r0b[q].z; f3 = r1b[q].x; }
            else {
                f0 = r0b[q].z; f1 = r0b[q].w;
                if (edge) { f2 = r1b[q].z; f3 = r1b[q].w; }
                else      { f2 = f8[q];    f3 = r1b[q].z; }
            }
            float m0, m1, m2, m3, n0, n1, n2, n3;
            qblock(c1, f0, f1, f2, f3, m0, m1, m2, m3);
            qblock(c2, m0, m1, m2, m3, n0, n1, n2, n3);
            float t0 = m0 + n0, t1 = m1 + n1, t2 = m2 + n2, t3 = m3 + n3;
            PK(zr[0][q], t0, t0);
            PK(zr[1][q], t1, t1);
            PK(zr[2][q], t2, t2);
            PK(zr[3][q], t3, t3);
        }
        const float4* wp = W4 + pbase + i;
        #pragma unroll
        for (int cp = 0; cp < NC / 2; cp++) {
            float4 wA = __ldg(wp + (size_t)(2 * cp)     * P);
            float4 wB = __ldg(wp + (size_t)(2 * cp + 1) * P);
            u64 wx, wy, wz, ww;
            PK(wx, wA.x, wB.x); PK(wy, wA.y, wB.y);
            PK(wz, wA.z, wB.z); PK(ww, wA.w, wB.w);
            #pragma unroll
            for (int q = 0; q < GB; q++) {
                FMA2(acc2[q][cp], zr[0][q], wx, acc2[q][cp]);
                FMA2(acc2[q][cp], zr[1][q], wy, acc2[q][cp]);
                FMA2(acc2[q][cp], zr[2][q], wz, acc2[q][cp]);
                FMA2(acc2[q][cp], zr[3][q], ww, acc2[q][cp]);
            }
        }
    }

    // ---- warp reduce packed pairs, then 2-warp combine via shared ----
    #pragma unroll
    for (int q = 0; q < GB; q++)
        #pragma unroll
        for (int cp = 0; cp < NC / 2; cp++) {
            u64 v = acc2[q][cp];
            #pragma unroll
            for (int off = 16; off > 0; off >>= 1) {
                u64 o = __shfl_down_sync(0xffffffffu, v, off);
                ADD2(v, v, o);
            }
            acc2[q][cp] = v;
        }

    __shared__ u64 sm2[2][GB * NC / 2];
    const int warp = tid >> 5, lane = tid & 31;
    if (lane == 0) {
        #pragma unroll
        for (int q = 0; q < GB; q++)
            #pragma unroll
            for (int cp = 0; cp < NC / 2; cp++)
                sm2[warp][q * (NC / 2) + cp] = acc2[q][cp];
    }
    __syncthreads();

    if (tid < GB * NC) {
        // float layout of sm2[w]: index q*10 + c  (pack lo = even class)
        const float* s0f = (const float*)sm2[0];
        const float* s1f = (const float*)sm2[1];
        const int q = tid / NC, c = tid - q * NC;
        float s = s0f[tid] + s1f[tid];
        g_part[(c * BATCH + (b0 + q)) * BLKS + blk] = s;
    }

    // ---- grid-wide finalize by last block ----
    __shared__ int lastFlag;
    __threadfence();
    __syncthreads();
    if (tid == 0) lastFlag = (atomicAdd(&g_ctr, 1u) == NBLOCKS - 1);
    __syncthreads();
    if (!lastFlag) return;

    __threadfence();   // acquire
    __shared__ float s_lg[BATCH][NC];
    #pragma unroll
    for (int u = tid; u < BATCH * NC; u += TPB) {     // 5 iterations/thread
        const int b = u / NC, c = u - b * NC;
        const float* base = g_part + (c * BATCH + b) * BLKS;   // 49 contiguous floats
        float s = __ldg(bias + c);
        #pragma unroll
        for (int k = 0; k < 12; k++) {
            float4 v = ldcg4(base + 4 * k);
            s += (v.x + v.y) + (v.z + v.w);
        }
        s += ldcg(base + 48);
        s_lg[b][c] = s;
    }
    __syncthreads();
    if (tid < BATCH) {
        float lg[NC];
        #pragma unroll
        for (int c = 0; c < NC; c++) lg[c] = s_lg[tid][c];
        float mx = lg[0];
        #pragma unroll
        for (int c = 1; c < NC; c++) mx = fmaxf(mx, lg[c]);
        float se = 0.f;
        #pragma unroll
        for (int c = 0; c < NC; c++) se += expf(lg[c] - mx);
        const float lse = logf(se);
        #pragma unroll
        for (int c = 0; c < NC; c++) out[tid * NC + c] = lg[c] - mx - lse;
    }
    if (tid == 0) g_ctr = 0;   // reset for next graph replay
}

extern "C" void kernel_launch(void* const* d_in, const int* in_sizes, int n_in,
                              void* d_out, int out_size) {
    const float* x    = (const float*)d_in[0];
    const float* rl1  = (const float*)d_in[1];
    const float* rl2  = (const float*)d_in[2];
    const float* W    = (const float*)d_in[3];
    const float* bias = (const float*)d_in[4];
    float* out        = (float*)d_out;

    k_fused<<<dim3(BLKX, NBG), TPB>>>(x, rl1, rl2, W, bias, out);
}

// round 7
// speedup vs baseline: 2.5635x; 1.0401x over previous
#include <cuda_runtime.h>
#include <math.h>

#define IMG    224
#define PSIDE  112
#define P      12544
#define BATCH  32
#define NC     10
#define KP     2                  // patches per thread (row-consecutive)
#define GB     4                  // batches per thread
#define ROWG   (PSIDE / KP)       // 56 patch-groups per row
#define PG     (P / KP)           // 6272 patch-groups
#define TPB    128
#define BLKX   (PG / TPB)         // 49
#define NBG    (BATCH / GB)       // 8
#define NBLOCKS (BLKX * NBG)      // 392
#define NWARP  (TPB / 32)         // 4
#define BLKS   52                 // padded stride (mult of 4) for g_part

typedef unsigned long long u64;

__device__ float    g_part[NC * BATCH * BLKS];
__device__ unsigned g_ctr = 0;

#define PK(d, lo, hi)    asm("mov.b64 %0, {%1, %2};" : "=l"(d) : "f"(lo), "f"(hi))
#define FMA2(d, a, b, c) asm("fma.rn.f32x2 %0, %1, %2, %3;" : "=l"(d) : "l"(a), "l"(b), "l"(c))
#define ADD2(d, a, b)    asm("add.rn.f32x2 %0, %1, %2;" : "=l"(d) : "l"(a), "l"(b))

__device__ __forceinline__ float ldcg(const float* p) {
    float v; asm volatile("ld.global.cg.f32 %0, [%1];" : "=f"(v) : "l"(p)); return v;
}
__device__ __forceinline__ float4 ldcg4(const float* p) {
    float4 v;
    asm volatile("ld.global.cg.v4.f32 {%0,%1,%2,%3}, [%4];"
                 : "=f"(v.x), "=f"(v.y), "=f"(v.z), "=f"(v.w) : "l"(p));
    return v;
}

// Closed-form 4-qubit block (circuit factorizes into pairs {0,1},{2,3};
// final RZ is a pure phase):
//   Z0 = cos(d0+p0);  Z1 = Z0 * cos(p1) * cos(d1)
//   Z2 = cos(p4)cos(d2) + sin(p2)sin(p4) * sin(d2) * sin(d3+p3)
//   Z3 = cos(d2) * cos(d3+p3)
// consts c[7] = {cos p0, sin p0, cos p1, cos p3, sin p3, cos p4, sin p2*sin p4}
__device__ __forceinline__ void qblock(const float c[7],
                                       float d0, float d1, float d2, float d3,
                                       float& z0, float& z1, float& z2, float& z3) {
    float s0, c0; __sincosf(d0, &s0, &c0);
    float cA = c0 * c[0] - s0 * c[1];
    z0 = cA;
    z1 = cA * c[2] * __cosf(d1);
    float s2, c2; __sincosf(d2, &s2, &c2);
    float s3, c3; __sincosf(d3, &s3, &c3);
    float cB = c3 * c[3] - s3 * c[4];
    float sB = s3 * c[3] + c3 * c[4];
    z2 = c[5] * c2 + c[6] * s2 * sB;
    z3 = c2 * cB;
}

__device__ __forceinline__ void make_consts(const float* __restrict__ prm, float c[7]) {
    float s, co;
    __sincosf(__ldg(prm + 0), &s, &co); c[0] = co; c[1] = s;
    c[2] = __cosf(__ldg(prm + 1));
    __sincosf(__ldg(prm + 3), &s, &co); c[3] = co; c[4] = s;
    float s4, c4; __sincosf(__ldg(prm + 4), &s4, &c4);
    c[5] = c4;
    c[6] = __sinf(__ldg(prm + 2)) * s4;
}

__global__ void __launch_bounds__(TPB)
k_fused(const float* __restrict__ x,
        const float* __restrict__ rl1, const float* __restrict__ rl2,
        const float* __restrict__ W,   const float* __restrict__ bias,
        float* __restrict__ out) {
    const int tid  = threadIdx.x;
    const int blk  = blockIdx.x;
    const int pg   = blk * TPB + tid;              // patch-group [0, 6272)
    const int b0   = blockIdx.y * GB;              // first batch
    const int r    = pg / ROWG;                    // patch row [0, 112)
    const int g    = pg - r * ROWG;                // group in row [0, 56)
    const bool edge = (g == ROWG - 1);

    float c1[7], c2[7];
    make_consts(rl1, c1);
    make_consts(rl2, c2);

    // x loads per batch: row0 cols [4g..4g+3] (+4g+4 non-edge), row1 cols [4g..4g+3]
    const float* Xb = x + (size_t)b0 * (IMG * IMG) + (2 * r) * IMG + g * (2 * KP);
    float4 r0[GB], r1[GB]; float e4[GB];
    #pragma unroll
    for (int q = 0; q < GB; q++) {
        const float* p0 = Xb + q * (IMG * IMG);
        r0[q] = *(const float4*)p0;
        r1[q] = *(const float4*)(p0 + IMG);
        e4[q] = edge ? 0.f : __ldg(p0 + 4);
    }

    // Packed accumulators: acc2[q][cp] = (class 2cp, class 2cp+1)
    u64 acc2[GB][NC / 2];
    #pragma unroll
    for (int q = 0; q < GB; q++)
        #pragma unroll
        for (int cp = 0; cp < NC / 2; cp++) acc2[q][cp] = 0ull;

    const float4* __restrict__ W4 = (const float4*)W;
    const int pbase = r * PSIDE + g * KP;

    #pragma unroll
    for (int i = 0; i < KP; i++) {
        u64 zr[4][GB];
        #pragma unroll
        for (int q = 0; q < GB; q++) {
            float f0, f1, f2, f3;
            if (i == 0) { f0 = r0[q].x; f1 = r0[q].y; f2 = r0[q].z; f3 = r1[q].x; }
            else {
                f0 = r0[q].z; f1 = r0[q].w;
                if (edge) { f2 = r1[q].z; f3 = r1[q].w; }
                else      { f2 = e4[q];   f3 = r1[q].z; }
            }
            float m0, m1, m2, m3, n0, n1, n2, n3;
            qblock(c1, f0, f1, f2, f3, m0, m1, m2, m3);
            qblock(c2, m0, m1, m2, m3, n0, n1, n2, n3);
            float t0 = m0 + n0, t1 = m1 + n1, t2 = m2 + n2, t3 = m3 + n3;
            PK(zr[0][q], t0, t0);
            PK(zr[1][q], t1, t1);
            PK(zr[2][q], t2, t2);
            PK(zr[3][q], t3, t3);
        }
        const float4* wp = W4 + pbase + i;
        #pragma unroll
        for (int cp = 0; cp < NC / 2; cp++) {
            float4 wA = __ldg(wp + (size_t)(2 * cp)     * P);
            float4 wB = __ldg(wp + (size_t)(2 * cp + 1) * P);
            u64 wx, wy, wz, ww;
            PK(wx, wA.x, wB.x); PK(wy, wA.y, wB.y);
            PK(wz, wA.z, wB.z); PK(ww, wA.w, wB.w);
            #pragma unroll
            for (int q = 0; q < GB; q++) {
                FMA2(acc2[q][cp], zr[0][q], wx, acc2[q][cp]);
                FMA2(acc2[q][cp], zr[1][q], wy, acc2[q][cp]);
                FMA2(acc2[q][cp], zr[2][q], wz, acc2[q][cp]);
                FMA2(acc2[q][cp], zr[3][q], ww, acc2[q][cp]);
            }
        }
    }

    // ---- warp reduce packed pairs, then cross-warp via shared ----
    #pragma unroll
    for (int q = 0; q < GB; q++)
        #pragma unroll
        for (int cp = 0; cp < NC / 2; cp++) {
            u64 v = acc2[q][cp];
            #pragma unroll
            for (int off = 16; off > 0; off >>= 1) {
                u64 o = __shfl_down_sync(0xffffffffu, v, off);
                ADD2(v, v, o);
            }
            acc2[q][cp] = v;
        }

    __shared__ u64 sm2[NWARP][GB * NC / 2];
    const int warp = tid >> 5, lane = tid & 31;
    if (lane == 0) {
        #pragma unroll
        for (int q = 0; q < GB; q++)
            #pragma unroll
            for (int cp = 0; cp < NC / 2; cp++)
                sm2[warp][q * (NC / 2) + cp] = acc2[q][cp];
    }
    __syncthreads();

    if (tid < GB * NC) {
        // float view of sm2[w]: index q*10 + c (pack lo = even class)
        const int q = tid / NC, c = tid - q * NC;
        float s = 0.f;
        #pragma unroll
        for (int w = 0; w < NWARP; w++)
            s += ((const float*)sm2[w])[tid];
        g_part[(c * BATCH + (b0 + q)) * BLKS + blk] = s;
    }

    // ---- grid-wide finalize by last block ----
    __shared__ int lastFlag;
    __threadfence();
    __syncthreads();
    if (tid == 0) lastFlag = (atomicAdd(&g_ctr, 1u) == NBLOCKS - 1);
    __syncthreads();
    if (!lastFlag) return;

    __threadfence();   // acquire
    __shared__ float s_lg[BATCH][NC];
    #pragma unroll
    for (int u = tid; u < BATCH * NC; u += TPB) {
        const int b = u / NC, c = u - b * NC;
        const float* base = g_part + (c * BATCH + b) * BLKS;   // 49 contiguous
        float s = __ldg(bias + c);
        #pragma unroll
        for (int k = 0; k < 12; k++) {
            float4 v = ldcg4(base + 4 * k);
            s += (v.x + v.y) + (v.z + v.w);
        }
        s += ldcg(base + 48);
        s_lg[b][c] = s;
    }
    __syncthreads();
    if (tid < BATCH) {
        float lg[NC];
        #pragma unroll
        for (int c = 0; c < NC; c++) lg[c] = s_lg[tid][c];
        float mx = lg[0];
        #pragma unroll
        for (int c = 1; c < NC; c++) mx = fmaxf(mx, lg[c]);
        float se = 0.f;
        #pragma unroll
        for (int c = 0; c < NC; c++) se += expf(lg[c] - mx);
        const float lse = logf(se);
        #pragma unroll
        for (int c = 0; c < NC; c++) out[tid * NC + c] = lg[c] - mx - lse;
    }
    if (tid == 0) g_ctr = 0;   // reset for next graph replay
}

extern "C" void kernel_launch(void* const* d_in, const int* in_sizes, int n_in,
                              void* d_out, int out_size) {
    const float* x    = (const float*)d_in[0];
    const float* rl1  = (const float*)d_in[1];
    const float* rl2  = (const float*)d_in[2];
    const float* W    = (const float*)d_in[3];
    const float* bias = (const float*)d_in[4];
    float* out        = (float*)d_out;

    k_fused<<<dim3(BLKX, NBG), TPB>>>(x, rl1, rl2, W, bias, out);
}